// round 1
// baseline (speedup 1.0000x reference)
#include <cuda_runtime.h>
#include <cuda_bf16.h>
#include <cstdint>

#define NN   8192
#define DIN  512
#define DOUT 512
#define NP   576      // padded B cols for agg GEMM: 512 features + 1 deg col + pad (9 tiles of 64)
#define A2K  1024     // [x | agg] concat width

// ---------------- scratch (__device__ globals; no allocations allowed) ----------------
__device__ __nv_bfloat16 g_bxt_hi[(size_t)NP * NN];   // x^T padded, bf16 hi  [n=576][k=8192]
__device__ __nv_bfloat16 g_bxt_lo[(size_t)NP * NN];   // x^T padded, bf16 lo
__device__ float         g_C1[(size_t)NN * NP];       // mask @ [x|1]  (fp32)
__device__ __nv_bfloat16 g_a2_hi[(size_t)NN * A2K];   // [x | agg] hi  [8192][1024]
__device__ __nv_bfloat16 g_a2_lo[(size_t)NN * A2K];
__device__ __nv_bfloat16 g_ws_hi[DIN * DOUT], g_ws_lo[DIN * DOUT];
__device__ __nv_bfloat16 g_wnb_hi[DIN * DOUT], g_wnb_lo[DIN * DOUT];
__device__ __nv_bfloat16 g_wcT_hi[DOUT * 1024], g_wcT_lo[DOUT * 1024];   // W_comb^T [n=512][k=1024]
__device__ __nv_bfloat16 g_wabT_hi[DOUT * 1024], g_wabT_lo[DOUT * 1024]; // fused weights^T [512][1024]
__device__ float         g_bias[DOUT];

// ---------------- helpers ----------------
__device__ __forceinline__ void split2(float v, __nv_bfloat16& h, __nv_bfloat16& l) {
    h = __float2bfloat16(v);
    l = __float2bfloat16(v - __bfloat162float(h));
}

__device__ __forceinline__ void mma_bf16(float* d,
                                         uint32_t a0, uint32_t a1, uint32_t a2, uint32_t a3,
                                         uint32_t b0, uint32_t b1) {
    asm volatile(
        "mma.sync.aligned.m16n8k16.row.col.f32.bf16.bf16.f32 "
        "{%0,%1,%2,%3},{%4,%5,%6,%7},{%8,%9},{%0,%1,%2,%3};\n"
        : "+f"(d[0]), "+f"(d[1]), "+f"(d[2]), "+f"(d[3])
        : "r"(a0), "r"(a1), "r"(a2), "r"(a3), "r"(b0), "r"(b1));
}

// ---------------- small prep kernels ----------------
__global__ void k_split_w(const float* __restrict__ ws, const float* __restrict__ wn) {
    int idx = blockIdx.x * blockDim.x + threadIdx.x;
    if (idx < DIN * DOUT) {
        split2(ws[idx], g_ws_hi[idx], g_ws_lo[idx]);
        split2(wn[idx], g_wnb_hi[idx], g_wnb_lo[idx]);
    }
}

// W_comb [1024][512] -> transposed split [512][1024]
__global__ void k_transpose_wc(const float* __restrict__ wc) {
    __shared__ float t[32][33];
    int n0 = blockIdx.x * 32, r0 = blockIdx.y * 32;
    for (int ii = threadIdx.y; ii < 32; ii += 8)
        t[ii][threadIdx.x] = wc[(size_t)(r0 + ii) * DOUT + n0 + threadIdx.x];
    __syncthreads();
    for (int jj = threadIdx.y; jj < 32; jj += 8) {
        int n = n0 + jj, k = r0 + threadIdx.x;
        __nv_bfloat16 h, l;
        split2(t[threadIdx.x][jj], h, l);
        g_wcT_hi[(size_t)n * 1024 + k] = h;
        g_wcT_lo[(size_t)n * 1024 + k] = l;
    }
}

// x [8192][512] -> x^T padded [576][8192], col 512 = ones (deg), 513.. = 0
__global__ void k_build_bxt(const float* __restrict__ x) {
    __shared__ float t[32][33];
    int n0 = blockIdx.x * 32, i0 = blockIdx.y * 32;
    for (int ii = threadIdx.y; ii < 32; ii += 8) {
        int j = n0 + threadIdx.x;
        float v;
        if (j < DIN) v = x[(size_t)(i0 + ii) * DIN + j];
        else         v = (j == DIN) ? 1.0f : 0.0f;
        t[ii][threadIdx.x] = v;
    }
    __syncthreads();
    for (int jj = threadIdx.y; jj < 32; jj += 8) {
        int n = n0 + jj, k = i0 + threadIdx.x;
        __nv_bfloat16 h, l;
        split2(t[threadIdx.x][jj], h, l);
        g_bxt_hi[(size_t)n * NN + k] = h;
        g_bxt_lo[(size_t)n * NN + k] = l;
    }
}

// x splits into A2 columns 0..511
__global__ void k_a2x(const float* __restrict__ x) {
    int idx = blockIdx.x * blockDim.x + threadIdx.x;
    if (idx < NN * DIN) {
        int i = idx >> 9, j = idx & 511;
        split2(x[idx], g_a2_hi[(size_t)i * A2K + j], g_a2_lo[(size_t)i * A2K + j]);
    }
}

// fused bias: b_self@Wc1 + b_nb@Wc2 + b_comb
__global__ void k_bias(const float* __restrict__ bs, const float* __restrict__ bn,
                       const float* __restrict__ bc, const float* __restrict__ wc) {
    int j = threadIdx.x;
    float s = bc[j];
    for (int k = 0; k < DIN; k++) {
        s += bs[k] * wc[(size_t)k * DOUT + j];
        s += bn[k] * wc[(size_t)(DIN + k) * DOUT + j];
    }
    g_bias[j] = s;
}

// C1 -> agg = C1/max(deg,1), write into A2 cols 512..1023 as bf16 splits
__global__ void k_epi() {
    int idx = blockIdx.x * blockDim.x + threadIdx.x;
    if (idx < NN * DIN) {
        int i = idx >> 9, j = idx & 511;
        float deg = g_C1[(size_t)i * NP + DIN];
        float r = 1.0f / fmaxf(deg, 1.0f);
        float v = g_C1[(size_t)i * NP + j] * r;
        split2(v, g_a2_hi[(size_t)i * A2K + 512 + j], g_a2_lo[(size_t)i * A2K + 512 + j]);
    }
}

// ---------------- big GEMM: C1[8192][576] = mask(adj) @ [x|1]  (bf16 split on B only) ----------------
// block 128x64, BK=64, 256 threads (8 warps: 4(M) x 2(N)), warp tile 32x32
__global__ void __launch_bounds__(256) agg_kernel(const int* __restrict__ adj) {
    __shared__ uint32_t As[128 * 36];   // mask tile, bf16 pairs, row stride 36 words (72 bf16)
    __shared__ uint32_t Bh[64 * 36];    // x_hi^T tile [n][k]
    __shared__ uint32_t Bl[64 * 36];    // x_lo^T tile

    int tid = threadIdx.x;
    int wid = tid >> 5, lane = tid & 31;
    int wm = wid >> 1, wn = wid & 1;
    int g = lane >> 2, tq = lane & 3;
    int m0 = blockIdx.y * 128, n0 = blockIdx.x * 64;

    float acc[2][4][4];
#pragma unroll
    for (int a = 0; a < 2; a++)
#pragma unroll
        for (int b = 0; b < 4; b++)
#pragma unroll
            for (int c = 0; c < 4; c++) acc[a][b][c] = 0.0f;

    for (int kt = 0; kt < NN; kt += 64) {
        // load adj tile 128x64 ints -> {0,1} bf16
#pragma unroll
        for (int i = 0; i < 8; i++) {
            int linear = tid + i * 256;
            int row = linear >> 4, c4 = linear & 15;
            int4 v = *reinterpret_cast<const int4*>(adj + (size_t)(m0 + row) * NN + kt + c4 * 4);
            uint32_t w0 = (v.x > 0 ? 0x3F80u : 0u) | (v.y > 0 ? 0x3F800000u : 0u);
            uint32_t w1 = (v.z > 0 ? 0x3F80u : 0u) | (v.w > 0 ? 0x3F800000u : 0u);
            *reinterpret_cast<uint2*>(&As[row * 36 + c4 * 2]) = make_uint2(w0, w1);
        }
        // load x^T tiles (already bf16, n-major)
#pragma unroll
        for (int i = 0; i < 2; i++) {
            int linear = tid + i * 256;
            int row = linear >> 3, c8 = linear & 7;
            *reinterpret_cast<int4*>(&Bh[row * 36 + c8 * 4]) =
                *reinterpret_cast<const int4*>(&g_bxt_hi[(size_t)(n0 + row) * NN + kt + c8 * 8]);
            *reinterpret_cast<int4*>(&Bl[row * 36 + c8 * 4]) =
                *reinterpret_cast<const int4*>(&g_bxt_lo[(size_t)(n0 + row) * NN + kt + c8 * 8]);
        }
        __syncthreads();

#pragma unroll
        for (int ks = 0; ks < 4; ks++) {
            int kw = ks * 8;
            uint32_t a[2][4];
#pragma unroll
            for (int im = 0; im < 2; im++) {
                int r = wm * 32 + im * 16 + g;
                a[im][0] = As[r * 36 + kw + tq];
                a[im][1] = As[(r + 8) * 36 + kw + tq];
                a[im][2] = As[r * 36 + kw + tq + 4];
                a[im][3] = As[(r + 8) * 36 + kw + tq + 4];
            }
#pragma unroll
            for (int in = 0; in < 4; in++) {
                int rn = wn * 32 + in * 8 + g;
                uint32_t bh0 = Bh[rn * 36 + kw + tq], bh1 = Bh[rn * 36 + kw + tq + 4];
                uint32_t bl0 = Bl[rn * 36 + kw + tq], bl1 = Bl[rn * 36 + kw + tq + 4];
#pragma unroll
                for (int im = 0; im < 2; im++) {
                    mma_bf16(acc[im][in], a[im][0], a[im][1], a[im][2], a[im][3], bh0, bh1);
                    mma_bf16(acc[im][in], a[im][0], a[im][1], a[im][2], a[im][3], bl0, bl1);
                }
            }
        }
        __syncthreads();
    }

#pragma unroll
    for (int im = 0; im < 2; im++)
#pragma unroll
        for (int in = 0; in < 4; in++) {
            int r = m0 + wm * 32 + im * 16 + g;
            int c = n0 + wn * 32 + in * 8 + tq * 2;
            float* o = g_C1 + (size_t)r * NP + c;
            o[0] = acc[im][in][0];
            o[1] = acc[im][in][1];
            o[(size_t)8 * NP] = acc[im][in][2];
            o[(size_t)8 * NP + 1] = acc[im][in][3];
        }
}

// ---------------- small split GEMM (3-term): weight fusion + final layer ----------------
// block 64x64, BK=64, 128 threads (4 warps: 2x2), warp tile 32x32
// mode 0: WabT[:, 0:512]    = (W_self @ Wc1)^T
// mode 1: WabT[:, 512:1024] = (W_nb  @ Wc2)^T
// mode 2: out = relu([x|agg] @ Wab + bias)
__global__ void __launch_bounds__(128) k_gemm2(int mode, float* __restrict__ out) {
    __shared__ uint32_t Ah[64 * 36];
    __shared__ uint32_t Al[64 * 36];
    __shared__ uint32_t Bh[64 * 36];
    __shared__ uint32_t Bl[64 * 36];

    const __nv_bfloat16 *ah, *al, *bh, *bl;
    int lda, ldb, K, moff;
    if (mode == 0) { ah = g_ws_hi;  al = g_ws_lo;  lda = 512;  bh = g_wcT_hi;       bl = g_wcT_lo;       ldb = 1024; K = 512;  moff = 0;   }
    else if (mode == 1) { ah = g_wnb_hi; al = g_wnb_lo; lda = 512;  bh = g_wcT_hi + 512; bl = g_wcT_lo + 512; ldb = 1024; K = 512;  moff = 512; }
    else { ah = g_a2_hi;  al = g_a2_lo;  lda = 1024; bh = g_wabT_hi;      bl = g_wabT_lo;      ldb = 1024; K = 1024; moff = 0;   }

    int tid = threadIdx.x;
    int wid = tid >> 5, lane = tid & 31;
    int wm = wid >> 1, wn = wid & 1;
    int g = lane >> 2, tq = lane & 3;
    int m0 = blockIdx.y * 64, n0 = blockIdx.x * 64;

    float acc[2][4][4];
#pragma unroll
    for (int a = 0; a < 2; a++)
#pragma unroll
        for (int b = 0; b < 4; b++)
#pragma unroll
            for (int c = 0; c < 4; c++) acc[a][b][c] = 0.0f;

    for (int kt = 0; kt < K; kt += 64) {
#pragma unroll
        for (int i = 0; i < 4; i++) {
            int linear = tid + i * 128;
            int row = linear >> 3, c8 = linear & 7;
            *reinterpret_cast<int4*>(&Ah[row * 36 + c8 * 4]) =
                *reinterpret_cast<const int4*>(&ah[(size_t)(m0 + row) * lda + kt + c8 * 8]);
            *reinterpret_cast<int4*>(&Al[row * 36 + c8 * 4]) =
                *reinterpret_cast<const int4*>(&al[(size_t)(m0 + row) * lda + kt + c8 * 8]);
            *reinterpret_cast<int4*>(&Bh[row * 36 + c8 * 4]) =
                *reinterpret_cast<const int4*>(&bh[(size_t)(n0 + row) * ldb + kt + c8 * 8]);
            *reinterpret_cast<int4*>(&Bl[row * 36 + c8 * 4]) =
                *reinterpret_cast<const int4*>(&bl[(size_t)(n0 + row) * ldb + kt + c8 * 8]);
        }
        __syncthreads();

#pragma unroll
        for (int ks = 0; ks < 4; ks++) {
            int kw = ks * 8;
            uint32_t aHi[2][4], aLo[2][4];
#pragma unroll
            for (int im = 0; im < 2; im++) {
                int r = wm * 32 + im * 16 + g;
                aHi[im][0] = Ah[r * 36 + kw + tq];
                aHi[im][1] = Ah[(r + 8) * 36 + kw + tq];
                aHi[im][2] = Ah[r * 36 + kw + tq + 4];
                aHi[im][3] = Ah[(r + 8) * 36 + kw + tq + 4];
                aLo[im][0] = Al[r * 36 + kw + tq];
                aLo[im][1] = Al[(r + 8) * 36 + kw + tq];
                aLo[im][2] = Al[r * 36 + kw + tq + 4];
                aLo[im][3] = Al[(r + 8) * 36 + kw + tq + 4];
            }
#pragma unroll
            for (int in = 0; in < 4; in++) {
                int rn = wn * 32 + in * 8 + g;
                uint32_t bh0 = Bh[rn * 36 + kw + tq], bh1 = Bh[rn * 36 + kw + tq + 4];
                uint32_t bl0 = Bl[rn * 36 + kw + tq], bl1 = Bl[rn * 36 + kw + tq + 4];
#pragma unroll
                for (int im = 0; im < 2; im++) {
                    mma_bf16(acc[im][in], aHi[im][0], aHi[im][1], aHi[im][2], aHi[im][3], bh0, bh1);
                    mma_bf16(acc[im][in], aHi[im][0], aHi[im][1], aHi[im][2], aHi[im][3], bl0, bl1);
                    mma_bf16(acc[im][in], aLo[im][0], aLo[im][1], aLo[im][2], aLo[im][3], bh0, bh1);
                }
            }
        }
        __syncthreads();
    }

#pragma unroll
    for (int im = 0; im < 2; im++)
#pragma unroll
        for (int in = 0; in < 4; in++) {
            int rr = m0 + wm * 32 + im * 16 + g;
            int cc = n0 + wn * 32 + in * 8 + tq * 2;
            if (mode < 2) {
                // store transposed splits into fused-weight matrix
#pragma unroll
                for (int e = 0; e < 4; e++) {
                    int r = rr + (e >> 1) * 8;
                    int c = cc + (e & 1);
                    __nv_bfloat16 h, l;
                    split2(acc[im][in][e], h, l);
                    g_wabT_hi[(size_t)c * 1024 + moff + r] = h;
                    g_wabT_lo[(size_t)c * 1024 + moff + r] = l;
                }
            } else {
#pragma unroll
                for (int e = 0; e < 4; e++) {
                    int r = rr + (e >> 1) * 8;
                    int c = cc + (e & 1);
                    float v = acc[im][in][e] + g_bias[c];
                    out[(size_t)r * DOUT + c] = fmaxf(v, 0.0f);
                }
            }
        }
}

// ---------------- launch ----------------
extern "C" void kernel_launch(void* const* d_in, const int* in_sizes, int n_in,
                              void* d_out, int out_size) {
    const float* x      = (const float*)d_in[0];
    const int*   adj    = (const int*)d_in[1];
    const float* W_self = (const float*)d_in[2];
    const float* b_self = (const float*)d_in[3];
    const float* W_nb   = (const float*)d_in[4];
    const float* b_nb   = (const float*)d_in[5];
    const float* W_comb = (const float*)d_in[6];
    const float* b_comb = (const float*)d_in[7];
    float* out = (float*)d_out;

    // prep (all independent of agg result)
    k_split_w<<<(DIN * DOUT + 255) / 256, 256>>>(W_self, W_nb);
    k_transpose_wc<<<dim3(16, 32), dim3(32, 8)>>>(W_comb);
    k_build_bxt<<<dim3(NP / 32, NN / 32), dim3(32, 8)>>>(x);
    k_a2x<<<(NN * DIN + 255) / 256, 256>>>(x);
    k_bias<<<1, DOUT>>>(b_self, b_nb, b_comb, W_comb);
    // fused weights
    k_gemm2<<<dim3(8, 8), 128>>>(0, nullptr);
    k_gemm2<<<dim3(8, 8), 128>>>(1, nullptr);
    // neighbor aggregation (dominant GEMM) + epilogue
    agg_kernel<<<dim3(NP / 64, NN / 128), 256>>>(adj);
    k_epi<<<(NN * DIN + 255) / 256, 256>>>();
    // final fused layer
    k_gemm2<<<dim3(DOUT / 64, NN / 64), 128>>>(2, out);
}